// round 15
// baseline (speedup 1.0000x reference)
#include <cuda_runtime.h>
#include <cuda_fp16.h>
#include <cstdint>

#define Hh 256
#define Ww 256
#define CIN 32
#define OCH 32
#define NB 4
#define NI 10
#define KOUT 8
#define XT 64
#define YT 16
#define NTH 1024

// A tile: [row 18][px 66][pair 16 + pad 4] u32 (f16x2), px pitch 20 u32 = 80B
#define AROWS 18
#define PXPITCH 20
#define ROWSTRIDE (66 * PXPITCH)    // 1320 u32

// ---- smem u32/float-index offsets ----
#define I_A    0                    // 23760
#define I_BF   23760                // 4608 -> 28368 (16B aligned)
#define I_GT   28368                // 2880 -> 31248
#define I_P    31248                // 90
#define I_W6   31344
#define I_W4   31376
#define I_INV  31408
#define I_OFC  31440
#define I_ACT  31472                // 10 int
#define I_B0   31482
#define I_INST 31484                // 80 -> 31564
#define I_SK   31568                // 2304 -> 33872
#define SMEM_TOTAL (33872 * 4)

__device__ int g_active[NB * NI];

__device__ __forceinline__ uint32_t pack_h2(float lo, float hi) {
    __half2 h = __floats2half2_rn(lo, hi);
    return *(uint32_t*)&h;
}
__device__ __forceinline__ uint32_t smem_u32(const void* p) {
    uint32_t a;
    asm("{ .reg .u64 t; cvta.to.shared.u64 t, %1; cvt.u32.u64 %0, t; }" : "=r"(a) : "l"(p));
    return a;
}
__device__ __forceinline__ void ldsm_x4(uint32_t& r0, uint32_t& r1, uint32_t& r2,
                                        uint32_t& r3, uint32_t addr) {
    asm volatile("ldmatrix.sync.aligned.m8n8.x4.shared.b16 {%0,%1,%2,%3}, [%4];"
                 : "=r"(r0), "=r"(r1), "=r"(r2), "=r"(r3) : "r"(addr));
}
__device__ __forceinline__ void mma_f16(float* d, uint32_t a0, uint32_t a1,
                                        uint32_t a2, uint32_t a3,
                                        uint32_t b0, uint32_t b1) {
    asm volatile(
        "mma.sync.aligned.m16n8k16.row.col.f32.f16.f16.f32 "
        "{%0,%1,%2,%3},{%4,%5,%6,%7},{%8,%9},{%0,%1,%2,%3};"
        : "+f"(d[0]), "+f"(d[1]), "+f"(d[2]), "+f"(d[3])
        : "r"(a0), "r"(a1), "r"(a2), "r"(a3), "r"(b0), "r"(b1));
}
__device__ __forceinline__ float sel4(float a0, float a1, float a2, float a3, int t) {
    return (t == 0) ? a0 : (t == 1) ? a1 : (t == 2) ? a2 : a3;
}

// ---------------- mask reduction with early exit ----------------
__global__ void mask_kernel(const int* __restrict__ masks) {
    const int m = blockIdx.x;
    const int4* p = (const int4*)(masks + (size_t)m * (Hh * Ww)) + blockIdx.y * 8192;
    int acc = 0;
#pragma unroll 1
    for (int batch = 0; batch < 4; batch++) {
#pragma unroll
        for (int k = 0; k < 8; k++) {
            int4 v = p[batch * 2048 + k * 256 + threadIdx.x];
            acc |= v.x | v.y | v.z | v.w;
        }
        if (__any_sync(0xffffffffu, acc)) break;
    }
    if (__syncthreads_or(acc)) {
        if (threadIdx.x == 0) g_active[m] = 1;
    }
}

// ---------------- fused prep + conv(mma f16 k16, ldmatrix) + BN + leaky + head ----------------
__global__ __launch_bounds__(NTH, 1)
void conv_mma_kernel(const float* __restrict__ x, const float* __restrict__ c1w,
                     const float* __restrict__ emb, const float* __restrict__ klin,
                     const float* __restrict__ gamma, const float* __restrict__ beta,
                     const float* __restrict__ mean, const float* __restrict__ var,
                     const float* __restrict__ c2w, const float* __restrict__ c2b,
                     float* __restrict__ out) {
    extern __shared__ float smf[];
    uint32_t* sA = (uint32_t*)smf;
    uint32_t* sBfU = (uint32_t*)(smf + I_BF);
    const uint4* sBf4 = (const uint4*)(smf + I_BF);
    float* sGT = smf + I_GT;
    float* sP = smf + I_P;
    float* sW6 = smf + I_W6;
    float* sW4 = smf + I_W4;
    float* sInv = smf + I_INV;
    float* sOfc = smf + I_OFC;
    int* sAct = (int*)(smf + I_ACT);
    float* sInst = smf + I_INST;
    float* sSk = smf + I_SK;

    const int tid = threadIdx.x;
    const int w = tid >> 5, lid = tid & 31;
    const int grp = lid >> 2, tg = lid & 3;
    const int row = w >> 1, mh = w & 1;   // warp covers row, px [mh*32, mh*32+32)
    const int b = blockIdx.z;
    const int X0 = blockIdx.x * XT;
    const int Y0 = blockIdx.y * YT;

    // ---- phase A: A tile [row][px][pair] (STS.64) + B frags + table scratch ----
    {
        const float* xb = x + (size_t)b * CIN * Hh * Ww;
        // main cols 0..63: each thread handles (row r, pair-pair pp) -> 4 channels
        {
            const int col = tid & 63;
            const int gx = X0 - 1 + col;
            const bool xok = (unsigned)gx < Ww;
#pragma unroll 3
            for (int idx = tid >> 6; idx < AROWS * 8; idx += 16) {
                const int r = idx >> 3;
                const int pp = idx & 7;
                const int gy = Y0 - 1 + r;
                float v0 = 0.f, v1 = 0.f, v2 = 0.f, v3 = 0.f;
                if (xok && (unsigned)gy < Hh) {
                    const float* pxl = xb + (size_t)(4 * pp) * (Hh * Ww) + gy * Ww + gx;
                    v0 = pxl[0];
                    v1 = pxl[Hh * Ww];
                    v2 = pxl[2 * Hh * Ww];
                    v3 = pxl[3 * Hh * Ww];
                }
                uint2 pk;
                pk.x = pack_h2(v0, v1);
                pk.y = pack_h2(v2, v3);
                *(uint2*)&sA[r * ROWSTRIDE + col * PXPITCH + 2 * pp] = pk;
            }
        }
        // edge cols 64,65
        for (int e = tid; e < AROWS * 16; e += NTH) {   // 288
            const int r = e >> 4;
            const int col = 64 + ((e >> 3) & 1);
            const int pp = e & 7;
            const int gy = Y0 - 1 + r;
            const int gx = X0 - 1 + col;
            float v0 = 0.f, v1 = 0.f, v2 = 0.f, v3 = 0.f;
            if ((unsigned)gy < Hh && (unsigned)gx < Ww) {
                const float* pxl = xb + (size_t)(4 * pp) * (Hh * Ww) + gy * Ww + gx;
                v0 = pxl[0];
                v1 = pxl[Hh * Ww];
                v2 = pxl[2 * Hh * Ww];
                v3 = pxl[3 * Hh * Ww];
            }
            uint2 pk;
            pk.x = pack_h2(v0, v1);
            pk.y = pack_h2(v2, v3);
            *(uint2*)&sA[r * ROWSTRIDE + col * PXPITCH + 2 * pp] = pk;
        }
    }
    // B fragments: [g][half=nt>>1][lane][4 u32]
    for (int e = tid; e < 18 * 4 * 32; e += NTH) {
        int lane = e & 31, nt = (e >> 5) & 3, g = e >> 7;
        int oc = nt * 8 + (lane >> 2);
        int tgl = lane & 3;
        int ks = g & 1, tap = g >> 1;
        const float* wp = c1w + (oc * 40) * 9 + tap;
        int c0 = ks * 16 + 2 * tgl;
        uint32_t b0 = pack_h2(wp[c0 * 9], wp[(c0 + 1) * 9]);
        uint32_t b1 = pack_h2(wp[(c0 + 8) * 9], wp[(c0 + 9) * 9]);
        int base = g * 256 + (nt >> 1) * 128 + lane * 4 + (nt & 1) * 2;
        sBfU[base] = b0;
        sBfU[base + 1] = b1;
    }
    if (tid < NI * KOUT) {
        int n = tid / KOUT, k = tid % KOUT;
        float s = 0.f;
#pragma unroll 8
        for (int i = 0; i < 64; i++) s += emb[n * 64 + i] * klin[k * 64 + i];
        sInst[tid] = s;
    }
    if (tid < OCH) {
        float iv = gamma[tid] * rsqrtf(var[tid] + 1e-5f);
        sInv[tid] = iv;
        sOfc[tid] = beta[tid] - mean[tid] * iv;
        float v = c2w[tid];
        sW6[tid] = 0.6f * v;
        sW4[tid] = 0.4f * v;
    }
    for (int e = tid; e < OCH * KOUT * 9; e += NTH) {
        int c = e / 72, k = (e / 9) % 8, cls = e % 9;
        int ry = cls / 3, rx = cls % 3;
        int dy0 = (ry == 0) ? 1 : 0, dy1 = (ry == 2) ? 1 : 2;
        int dx0 = (rx == 0) ? 1 : 0, dx1 = (rx == 2) ? 1 : 2;
        float s = 0.f;
        for (int dy = dy0; dy <= dy1; dy++)
            for (int dx = dx0; dx <= dx1; dx++)
                s += c1w[(c * 40 + (CIN + k)) * 9 + dy * 3 + dx];
        sSk[e] = s;
    }
    if (tid < NI) sAct[tid] = g_active[b * NI + tid];
    if (tid == 0) smf[I_B0] = c2b[0];
    __syncthreads();

    // ---- gtab ----
    for (int e = tid; e < NI * 9 * OCH; e += NTH) {
        int n = e / (9 * OCH), cls = (e / OCH) % 9, c = e % OCH;
        float s = 0.f;
#pragma unroll
        for (int k = 0; k < KOUT; k++) s += sInst[n * KOUT + k] * sSk[c * 72 + k * 9 + cls];
        sGT[e] = sInv[c] * s;
    }
    __syncthreads();
    if (tid < NI * 9) {
        int n = tid / 9, cls = tid % 9;
        float s = 0.f;
#pragma unroll 8
        for (int c = 0; c < OCH; c++) s += sW6[c] * sGT[(n * 9 + cls) * OCH + c];
        sP[tid] = s;
    }

    // ---- MMA mainloop (fully unrolled, f16 k16 + ldmatrix): 32 px x 32 oc ----
    float d[2][4][4];
#pragma unroll
    for (int mt = 0; mt < 2; mt++)
#pragma unroll
        for (int nt = 0; nt < 4; nt++)
#pragma unroll
            for (int r = 0; r < 4; r++) d[mt][nt][r] = 0.f;

    const uint32_t aLane = smem_u32(smf) +
        (uint32_t)(((row * ROWSTRIDE) + (mh * 32 + (lid & 15)) * PXPITCH) * 4 + (lid >> 4) * 16);

#pragma unroll
    for (int tap = 0; tap < 9; tap++) {
        const int dy = tap / 3, dx = tap % 3;
#pragma unroll
        for (int ks = 0; ks < 2; ks++) {
            const int g = tap * 2 + ks;
            const uint32_t ab = aLane + (uint32_t)(dy * (ROWSTRIDE * 4) + dx * (PXPITCH * 4) + ks * 32);
            uint4 q0 = sBf4[g * 64 + lid];
            uint4 q1 = sBf4[g * 64 + 32 + lid];
#pragma unroll
            for (int mt = 0; mt < 2; mt++) {
                uint32_t a0, a1, a2, a3;
                ldsm_x4(a0, a1, a2, a3, ab + (uint32_t)(mt * (16 * PXPITCH * 4)));
                mma_f16(d[mt][0], a0, a1, a2, a3, q0.x, q0.y);
                mma_f16(d[mt][1], a0, a1, a2, a3, q0.z, q0.w);
                mma_f16(d[mt][2], a0, a1, a2, a3, q1.x, q1.y);
                mma_f16(d[mt][3], a0, a1, a2, a3, q1.z, q1.w);
            }
        }
    }
    __syncthreads();  // sP ready for epilogue

    // ---- fragment-resident epilogue ----
    const int gy = Y0 + row;
    const int ry = (gy == 0) ? 0 : ((gy == Hh - 1) ? 2 : 1);
    const int clsM = ry * 3 + 1, cls0 = ry * 3, cls2 = ry * 3 + 2;
    const float b0 = smf[I_B0];
    const bool leftE = (X0 == 0) && (grp == 0) && (mh == 0);
    const bool rightE = (X0 + XT == Ww) && (grp == 7) && (mh == 1);

    float2 w62[4], w42[4];
#pragma unroll
    for (int nt = 0; nt < 4; nt++) {
        int oi = nt * 8 + tg * 2;
        w62[nt] = *(const float2*)(sW6 + oi);
        w42[nt] = *(const float2*)(sW4 + oi);
    }
    {
#pragma unroll
        for (int nt = 0; nt < 4; nt++) {
            int oi = nt * 8 + tg * 2;
            float2 iv = *(const float2*)(sInv + oi);
            float2 of = *(const float2*)(sOfc + oi);
#pragma unroll
            for (int mt = 0; mt < 2; mt++) {
                d[mt][nt][0] = fmaf(d[mt][nt][0], iv.x, of.x);
                d[mt][nt][1] = fmaf(d[mt][nt][1], iv.y, of.y);
                d[mt][nt][2] = fmaf(d[mt][nt][2], iv.x, of.x);
                d[mt][nt][3] = fmaf(d[mt][nt][3], iv.y, of.y);
            }
        }
    }

    float Lp[2][2];
#pragma unroll
    for (int mt = 0; mt < 2; mt++) {
        float la = 0.f, lb = 0.f;
#pragma unroll
        for (int nt = 0; nt < 4; nt++) {
            la = fmaf(w62[nt].x, d[mt][nt][0], la);
            la = fmaf(w62[nt].y, d[mt][nt][1], la);
            lb = fmaf(w62[nt].x, d[mt][nt][2], lb);
            lb = fmaf(w62[nt].y, d[mt][nt][3], lb);
        }
        Lp[mt][0] = la;
        Lp[mt][1] = lb;
    }
#pragma unroll
    for (int mt = 0; mt < 2; mt++)
#pragma unroll
        for (int h = 0; h < 2; h++) {
            Lp[mt][h] += __shfl_xor_sync(0xffffffffu, Lp[mt][h], 1);
            Lp[mt][h] += __shfl_xor_sync(0xffffffffu, Lp[mt][h], 2);
        }
    // my output slot j = tg: mt = j&1, h = j>>1
    const float Lpsel = sel4(Lp[0][0], Lp[1][0], Lp[0][1], Lp[1][1], tg);

    // this lane's output px within the tile row
    const int pxo = mh * 32 + (tg & 1) * 16 + ((tg >> 1) << 3) + grp;

#pragma unroll 2
    for (int n = 0; n < NI; n++) {
        float* op = out + (size_t)(b * NI + n) * (Hh * Ww) + (size_t)gy * Ww + X0;
        float vsel = 0.f;
        if (sAct[n]) {
            const float* gn = sGT + (n * 9 + clsM) * OCH;
            float2 g2[4];
#pragma unroll
            for (int nt = 0; nt < 4; nt++) g2[nt] = *(const float2*)(gn + nt * 8 + tg * 2);
            float acc[2][2];
#pragma unroll
            for (int mt = 0; mt < 2; mt++) {
                float a0 = 0.f, a1 = 0.f;
#pragma unroll
                for (int nt = 0; nt < 4; nt++) {
                    a0 = fmaf(w42[nt].x, fabsf(d[mt][nt][0] + g2[nt].x), a0);
                    a0 = fmaf(w42[nt].y, fabsf(d[mt][nt][1] + g2[nt].y), a0);
                    a1 = fmaf(w42[nt].x, fabsf(d[mt][nt][2] + g2[nt].x), a1);
                    a1 = fmaf(w42[nt].y, fabsf(d[mt][nt][3] + g2[nt].y), a1);
                }
                acc[mt][0] = a0;
                acc[mt][1] = a1;
            }
            if (leftE) {
                const float* ge = sGT + (n * 9 + cls0) * OCH;
                float a0 = 0.f;
#pragma unroll
                for (int nt = 0; nt < 4; nt++) {
                    float2 g = *(const float2*)(ge + nt * 8 + tg * 2);
                    a0 = fmaf(w42[nt].x, fabsf(d[0][nt][0] + g.x), a0);
                    a0 = fmaf(w42[nt].y, fabsf(d[0][nt][1] + g.y), a0);
                }
                acc[0][0] = a0;
            }
            if (rightE) {
                const float* ge = sGT + (n * 9 + cls2) * OCH;
                float a1 = 0.f;
#pragma unroll
                for (int nt = 0; nt < 4; nt++) {
                    float2 g = *(const float2*)(ge + nt * 8 + tg * 2);
                    a1 = fmaf(w42[nt].x, fabsf(d[1][nt][2] + g.x), a1);
                    a1 = fmaf(w42[nt].y, fabsf(d[1][nt][3] + g.y), a1);
                }
                acc[1][1] = a1;
            }
            // 3-shfl quad reduction (bitwise-identical grouping to old butterfly)
            const float v0 = acc[0][0], v1 = acc[1][0], v2 = acc[0][1], v3 = acc[1][1];
            float sa = sel4(v0, v1, v2, v3, tg) +
                       __shfl_xor_sync(0xffffffffu, sel4(v1, v0, v3, v2, tg), 1);
            float sb = sel4(v2, v3, v0, v1, tg) +
                       __shfl_xor_sync(0xffffffffu, sel4(v3, v2, v1, v0, tg), 1);
            float r = sa + __shfl_xor_sync(0xffffffffu, sb, 2);

            float Pv = sP[n * 9 + clsM];
            if (leftE && tg == 0) Pv = sP[n * 9 + cls0];
            if (rightE && tg == 3) Pv = sP[n * 9 + cls2];
            vsel = Lpsel + r + b0 + Pv;
        }
        op[pxo] = vsel;
    }
}

// ---------------- launch ----------------
extern "C" void kernel_launch(void* const* d_in, const int* in_sizes, int n_in,
                              void* d_out, int out_size) {
    const float* x = (const float*)d_in[0];
    const int* masks = (const int*)d_in[1];
    const float* emb = (const float*)d_in[2];
    const float* klin = (const float*)d_in[3];
    const float* c1w = (const float*)d_in[4];
    const float* gamma = (const float*)d_in[5];
    const float* beta = (const float*)d_in[6];
    const float* mean = (const float*)d_in[7];
    const float* var = (const float*)d_in[8];
    const float* c2w = (const float*)d_in[9];
    const float* c2b = (const float*)d_in[10];
    float* out = (float*)d_out;

    mask_kernel<<<dim3(NB * NI, 2), 256>>>(masks);

    cudaFuncSetAttribute(conv_mma_kernel, cudaFuncAttributeMaxDynamicSharedMemorySize,
                         SMEM_TOTAL);
    conv_mma_kernel<<<dim3(Ww / XT, Hh / YT, NB), NTH, SMEM_TOTAL>>>(
        x, c1w, emb, klin, gamma, beta, mean, var, c2w, c2b, out);
}

// round 17
// speedup vs baseline: 1.1943x; 1.1943x over previous
#include <cuda_runtime.h>
#include <cuda_fp16.h>
#include <cstdint>

#define Hh 256
#define Ww 256
#define CIN 32
#define OCH 32
#define NB 4
#define NI 10
#define KOUT 8
#define XT 64
#define YT 16
#define NTH 1024

// A tile: [row 18][px 66][pair 16 + pad 4] u32 (f16x2), px pitch 20 u32 = 80B
#define AROWS 18
#define PXPITCH 20
#define ROWSTRIDE (66 * PXPITCH)    // 1320 u32

// ---- smem u32/float-index offsets ----
#define I_A    0                    // 23760
#define I_BF   23760                // 4608 -> 28368
#define I_GT   28368                // 2880 -> 31248
#define I_P    31248                // 90
#define I_W6   31344
#define I_W4   31376
#define I_INV  31408
#define I_OFC  31440
#define I_ACT  31472                // 20 int (2 b's)
#define I_B0   31492
#define I_INST 31496                // 80 -> 31576
#define I_SK   31576                // 2304 -> 33880
#define SMEM_TOTAL (33880 * 4)

__device__ int g_active[NB * NI];

__device__ __forceinline__ uint32_t pack_h2(float lo, float hi) {
    __half2 h = __floats2half2_rn(lo, hi);
    return *(uint32_t*)&h;
}
__device__ __forceinline__ uint32_t smem_u32(const void* p) {
    uint32_t a;
    asm("{ .reg .u64 t; cvta.to.shared.u64 t, %1; cvt.u32.u64 %0, t; }" : "=r"(a) : "l"(p));
    return a;
}
__device__ __forceinline__ void ldsm_x4(uint32_t& r0, uint32_t& r1, uint32_t& r2,
                                        uint32_t& r3, uint32_t addr) {
    asm volatile("ldmatrix.sync.aligned.m8n8.x4.shared.b16 {%0,%1,%2,%3}, [%4];"
                 : "=r"(r0), "=r"(r1), "=r"(r2), "=r"(r3) : "r"(addr));
}
__device__ __forceinline__ void mma_f16(float* d, uint32_t a0, uint32_t a1,
                                        uint32_t a2, uint32_t a3,
                                        uint32_t b0, uint32_t b1) {
    asm volatile(
        "mma.sync.aligned.m16n8k16.row.col.f32.f16.f16.f32 "
        "{%0,%1,%2,%3},{%4,%5,%6,%7},{%8,%9},{%0,%1,%2,%3};"
        : "+f"(d[0]), "+f"(d[1]), "+f"(d[2]), "+f"(d[3])
        : "r"(a0), "r"(a1), "r"(a2), "r"(a3), "r"(b0), "r"(b1));
}

// ---------------- mask reduction with early exit ----------------
__global__ void mask_kernel(const int* __restrict__ masks) {
    const int m = blockIdx.x;
    const int4* p = (const int4*)(masks + (size_t)m * (Hh * Ww)) + blockIdx.y * 8192;
    int acc = 0;
#pragma unroll 1
    for (int batch = 0; batch < 4; batch++) {
#pragma unroll
        for (int k = 0; k < 8; k++) {
            int4 v = p[batch * 2048 + k * 256 + threadIdx.x];
            acc |= v.x | v.y | v.z | v.w;
        }
        if (__any_sync(0xffffffffu, acc)) break;
    }
    if (__syncthreads_or(acc)) {
        if (threadIdx.x == 0) g_active[m] = 1;
    }
}

// ---------------- fused prep + conv(mma f16 k16, ldmatrix) + BN + leaky + head ----------------
__global__ __launch_bounds__(NTH, 1)
void conv_mma_kernel(const float* __restrict__ x, const float* __restrict__ c1w,
                     const float* __restrict__ emb, const float* __restrict__ klin,
                     const float* __restrict__ gamma, const float* __restrict__ beta,
                     const float* __restrict__ mean, const float* __restrict__ var,
                     const float* __restrict__ c2w, const float* __restrict__ c2b,
                     float* __restrict__ out) {
    extern __shared__ float smf[];
    uint32_t* sA = (uint32_t*)smf;
    uint32_t* sBfU = (uint32_t*)(smf + I_BF);
    const uint2* sBf2 = (const uint2*)(smf + I_BF);
    float* sGT = smf + I_GT;
    float* sP = smf + I_P;
    float* sW6 = smf + I_W6;
    float* sW4 = smf + I_W4;
    float* sInv = smf + I_INV;
    float* sOfc = smf + I_OFC;
    int* sAct = (int*)(smf + I_ACT);
    float* sInst = smf + I_INST;
    float* sSk = smf + I_SK;

    const int tid = threadIdx.x;
    const int w = tid >> 5, lid = tid & 31;
    const int grp = lid >> 2, tg = lid & 3;
    const int row = w >> 1, mh = w & 1;   // warp covers row, px [mh*32, mh*32+32)
    const int bz = blockIdx.z;
    const int X0 = blockIdx.x * XT;
    const int Y0 = blockIdx.y * YT;

    // ---- one-time tables: B frags + scalars + Sk ----
    for (int e = tid; e < 18 * 4 * 32; e += NTH) {
        int lane = e & 31, nt = (e >> 5) & 3, g = e >> 7;
        int ks = g & 1, tap = g >> 1;
        int oc = nt * 8 + (lane >> 2);
        int tgl = lane & 3;
        const float* wp = c1w + (oc * 40) * 9 + tap;
        int c0 = ks * 16 + 2 * tgl;
        uint32_t b0 = pack_h2(wp[c0 * 9], wp[(c0 + 1) * 9]);
        uint32_t b1 = pack_h2(wp[(c0 + 8) * 9], wp[(c0 + 9) * 9]);
        sBfU[e * 2] = b0;
        sBfU[e * 2 + 1] = b1;
    }
    if (tid < NI * KOUT) {
        int n = tid / KOUT, k = tid % KOUT;
        float s = 0.f;
#pragma unroll 8
        for (int i = 0; i < 64; i++) s += emb[n * 64 + i] * klin[k * 64 + i];
        sInst[tid] = s;
    }
    if (tid < OCH) {
        float iv = gamma[tid] * rsqrtf(var[tid] + 1e-5f);
        sInv[tid] = iv;
        sOfc[tid] = beta[tid] - mean[tid] * iv;
        float v = c2w[tid];
        sW6[tid] = 0.6f * v;
        sW4[tid] = 0.4f * v;
    }
    for (int e = tid; e < OCH * KOUT * 9; e += NTH) {
        int c = e / 72, k = (e / 9) % 8, cls = e % 9;
        int ry = cls / 3, rx = cls % 3;
        int dy0 = (ry == 0) ? 1 : 0, dy1 = (ry == 2) ? 1 : 2;
        int dx0 = (rx == 0) ? 1 : 0, dx1 = (rx == 2) ? 1 : 2;
        float s = 0.f;
        for (int dy = dy0; dy <= dy1; dy++)
            for (int dx = dx0; dx <= dx1; dx++)
                s += c1w[(c * 40 + (CIN + k)) * 9 + dy * 3 + dx];
        sSk[e] = s;
    }
    if (tid < 2 * NI) sAct[tid] = g_active[(bz * 2 + tid / NI) * NI + (tid % NI)];
    if (tid == 0) smf[I_B0] = c2b[0];
    __syncthreads();

    for (int e = tid; e < NI * 9 * OCH; e += NTH) {
        int n = e / (9 * OCH), cls = (e / OCH) % 9, c = e % OCH;
        float s = 0.f;
#pragma unroll
        for (int k = 0; k < KOUT; k++) s += sInst[n * KOUT + k] * sSk[c * 72 + k * 9 + cls];
        sGT[e] = sInv[c] * s;
    }
    __syncthreads();
    if (tid < NI * 9) {
        int n = tid / 9, cls = tid % 9;
        float s = 0.f;
#pragma unroll 8
        for (int c = 0; c < OCH; c++) s += sW6[c] * sGT[(n * 9 + cls) * OCH + c];
        sP[tid] = s;
    }

    // epilogue constants (pass-invariant)
    const int gy = Y0 + row;
    const int ry = (gy == 0) ? 0 : ((gy == Hh - 1) ? 2 : 1);
    const int clsM = ry * 3 + 1, cls0 = ry * 3, cls2 = ry * 3 + 2;
    const bool leftE = (X0 == 0) && (grp == 0) && (mh == 0);
    const bool rightE = (X0 + XT == Ww) && (grp == 7) && (mh == 1);
    const uint32_t aLane = smem_u32(smf) +
        (uint32_t)(((row * ROWSTRIDE) + (mh * 32 + (lid & 15)) * PXPITCH) * 4 + (lid >> 4) * 16);
    const int pxo = mh * 32 + (tg & 1) * 16 + ((tg >> 1) << 3) + grp;

#pragma unroll 1
    for (int pass = 0; pass < 2; pass++) {
        const int b = bz * 2 + pass;

        // ---- A tile load for this b ----
        {
            const float* xb = x + (size_t)b * CIN * Hh * Ww;
            {
                const int col = tid & 63;
                const int gx = X0 - 1 + col;
                const bool xok = (unsigned)gx < Ww;
#pragma unroll 3
                for (int idx = tid >> 6; idx < AROWS * 16; idx += 16) {
                    const int r = idx >> 4;
                    const int pair = idx & 15;
                    const int gyy = Y0 - 1 + r;
                    float v0 = 0.f, v1 = 0.f;
                    if (xok && (unsigned)gyy < Hh) {
                        const float* pxl = xb + (size_t)(2 * pair) * (Hh * Ww) + gyy * Ww + gx;
                        v0 = pxl[0];
                        v1 = pxl[Hh * Ww];
                    }
                    sA[r * ROWSTRIDE + col * PXPITCH + pair] = pack_h2(v0, v1);
                }
            }
            for (int e = tid; e < AROWS * 16 * 2; e += NTH) {
                const int col = 64 + (e & 1);
                const int idx = e >> 1;
                const int r = idx >> 4;
                const int pair = idx & 15;
                const int gyy = Y0 - 1 + r;
                const int gx = X0 - 1 + col;
                float v0 = 0.f, v1 = 0.f;
                if ((unsigned)gyy < Hh && (unsigned)gx < Ww) {
                    const float* pxl = xb + (size_t)(2 * pair) * (Hh * Ww) + gyy * Ww + gx;
                    v0 = pxl[0];
                    v1 = pxl[Hh * Ww];
                }
                sA[r * ROWSTRIDE + col * PXPITCH + pair] = pack_h2(v0, v1);
            }
        }
        __syncthreads();

        // ---- MMA mainloop ----
        float d[2][4][4];
#pragma unroll
        for (int mt = 0; mt < 2; mt++)
#pragma unroll
            for (int nt = 0; nt < 4; nt++)
#pragma unroll
                for (int r = 0; r < 4; r++) d[mt][nt][r] = 0.f;

#pragma unroll
        for (int tap = 0; tap < 9; tap++) {
            const int dy = tap / 3, dx = tap % 3;
#pragma unroll
            for (int ks = 0; ks < 2; ks++) {
                const int g = tap * 2 + ks;
                const uint32_t ab = aLane +
                    (uint32_t)(dy * (ROWSTRIDE * 4) + dx * (PXPITCH * 4) + ks * 32);
                uint2 bf0 = sBf2[(g * 4 + 0) * 32 + lid];
                uint2 bf1 = sBf2[(g * 4 + 1) * 32 + lid];
                uint2 bf2 = sBf2[(g * 4 + 2) * 32 + lid];
                uint2 bf3 = sBf2[(g * 4 + 3) * 32 + lid];
#pragma unroll
                for (int mt = 0; mt < 2; mt++) {
                    uint32_t a0, a1, a2, a3;
                    ldsm_x4(a0, a1, a2, a3, ab + (uint32_t)(mt * (16 * PXPITCH * 4)));
                    mma_f16(d[mt][0], a0, a1, a2, a3, bf0.x, bf0.y);
                    mma_f16(d[mt][1], a0, a1, a2, a3, bf1.x, bf1.y);
                    mma_f16(d[mt][2], a0, a1, a2, a3, bf2.x, bf2.y);
                    mma_f16(d[mt][3], a0, a1, a2, a3, bf3.x, bf3.y);
                }
            }
        }
        __syncthreads();  // all reads of sA done; next pass may overwrite

        // ---- fragment-resident epilogue ----
        const float b0 = smf[I_B0];
        float2 w62[4], w42[4];
#pragma unroll
        for (int nt = 0; nt < 4; nt++) {
            int oi = nt * 8 + tg * 2;
            w62[nt] = *(const float2*)(sW6 + oi);
            w42[nt] = *(const float2*)(sW4 + oi);
        }
#pragma unroll
        for (int nt = 0; nt < 4; nt++) {
            int oi = nt * 8 + tg * 2;
            float2 iv = *(const float2*)(sInv + oi);
            float2 of = *(const float2*)(sOfc + oi);
#pragma unroll
            for (int mt = 0; mt < 2; mt++) {
                d[mt][nt][0] = fmaf(d[mt][nt][0], iv.x, of.x);
                d[mt][nt][1] = fmaf(d[mt][nt][1], iv.y, of.y);
                d[mt][nt][2] = fmaf(d[mt][nt][2], iv.x, of.x);
                d[mt][nt][3] = fmaf(d[mt][nt][3], iv.y, of.y);
            }
        }

        float Lp[2][2];
#pragma unroll
        for (int mt = 0; mt < 2; mt++) {
            float la = 0.f, lb = 0.f;
#pragma unroll
            for (int nt = 0; nt < 4; nt++) {
                la = fmaf(w62[nt].x, d[mt][nt][0], la);
                la = fmaf(w62[nt].y, d[mt][nt][1], la);
                lb = fmaf(w62[nt].x, d[mt][nt][2], lb);
                lb = fmaf(w62[nt].y, d[mt][nt][3], lb);
            }
            Lp[mt][0] = la;
            Lp[mt][1] = lb;
        }
#pragma unroll
        for (int mt = 0; mt < 2; mt++)
#pragma unroll
            for (int h = 0; h < 2; h++) {
                Lp[mt][h] += __shfl_xor_sync(0xffffffffu, Lp[mt][h], 1);
                Lp[mt][h] += __shfl_xor_sync(0xffffffffu, Lp[mt][h], 2);
            }

#pragma unroll 2
        for (int n = 0; n < NI; n++) {
            float* op = out + (size_t)(b * NI + n) * (Hh * Ww) + (size_t)gy * Ww + X0;
            float vsel = 0.f;
            if (sAct[pass * NI + n]) {
                const float* gn = sGT + (n * 9 + clsM) * OCH;
                float2 g2[4];
#pragma unroll
                for (int nt = 0; nt < 4; nt++) g2[nt] = *(const float2*)(gn + nt * 8 + tg * 2);
                float acc[2][2];
#pragma unroll
                for (int mt = 0; mt < 2; mt++) {
                    float a0 = 0.f, a1 = 0.f;
#pragma unroll
                    for (int nt = 0; nt < 4; nt++) {
                        a0 = fmaf(w42[nt].x, fabsf(d[mt][nt][0] + g2[nt].x), a0);
                        a0 = fmaf(w42[nt].y, fabsf(d[mt][nt][1] + g2[nt].y), a0);
                        a1 = fmaf(w42[nt].x, fabsf(d[mt][nt][2] + g2[nt].x), a1);
                        a1 = fmaf(w42[nt].y, fabsf(d[mt][nt][3] + g2[nt].y), a1);
                    }
                    acc[mt][0] = a0;
                    acc[mt][1] = a1;
                }
                if (leftE) {
                    const float* ge = sGT + (n * 9 + cls0) * OCH;
                    float a0 = 0.f;
#pragma unroll
                    for (int nt = 0; nt < 4; nt++) {
                        float2 g = *(const float2*)(ge + nt * 8 + tg * 2);
                        a0 = fmaf(w42[nt].x, fabsf(d[0][nt][0] + g.x), a0);
                        a0 = fmaf(w42[nt].y, fabsf(d[0][nt][1] + g.y), a0);
                    }
                    acc[0][0] = a0;
                }
                if (rightE) {
                    const float* ge = sGT + (n * 9 + cls2) * OCH;
                    float a1 = 0.f;
#pragma unroll
                    for (int nt = 0; nt < 4; nt++) {
                        float2 g = *(const float2*)(ge + nt * 8 + tg * 2);
                        a1 = fmaf(w42[nt].x, fabsf(d[1][nt][2] + g.x), a1);
                        a1 = fmaf(w42[nt].y, fabsf(d[1][nt][3] + g.y), a1);
                    }
                    acc[1][1] = a1;
                }
#pragma unroll
                for (int mt = 0; mt < 2; mt++)
#pragma unroll
                    for (int h = 0; h < 2; h++) {
                        acc[mt][h] += __shfl_xor_sync(0xffffffffu, acc[mt][h], 1);
                        acc[mt][h] += __shfl_xor_sync(0xffffffffu, acc[mt][h], 2);
                    }
                const float Pm = sP[n * 9 + clsM];
                const float P00 = leftE ? sP[n * 9 + cls0] : Pm;
                const float P11 = rightE ? sP[n * 9 + cls2] : Pm;
                float f[2][2];
#pragma unroll
                for (int mt = 0; mt < 2; mt++)
#pragma unroll
                    for (int h = 0; h < 2; h++) {
                        float Pv = (mt == 0 && h == 0) ? P00 : ((mt == 1 && h == 1) ? P11 : Pm);
                        f[mt][h] = Lp[mt][h] + acc[mt][h] + b0 + Pv;
                    }
                vsel = (tg & 1) ? ((tg >> 1) ? f[1][1] : f[1][0])
                                : ((tg >> 1) ? f[0][1] : f[0][0]);
            }
            op[pxo] = vsel;
        }
    }
}

// ---------------- launch ----------------
extern "C" void kernel_launch(void* const* d_in, const int* in_sizes, int n_in,
                              void* d_out, int out_size) {
    const float* x = (const float*)d_in[0];
    const int* masks = (const int*)d_in[1];
    const float* emb = (const float*)d_in[2];
    const float* klin = (const float*)d_in[3];
    const float* c1w = (const float*)d_in[4];
    const float* gamma = (const float*)d_in[5];
    const float* beta = (const float*)d_in[6];
    const float* mean = (const float*)d_in[7];
    const float* var = (const float*)d_in[8];
    const float* c2w = (const float*)d_in[9];
    const float* c2b = (const float*)d_in[10];
    float* out = (float*)d_out;

    mask_kernel<<<dim3(NB * NI, 2), 256>>>(masks);

    cudaFuncSetAttribute(conv_mma_kernel, cudaFuncAttributeMaxDynamicSharedMemorySize,
                         SMEM_TOTAL);
    conv_mma_kernel<<<dim3(Ww / XT, Hh / YT, NB / 2), NTH, SMEM_TOTAL>>>(
        x, c1w, emb, klin, gamma, beta, mean, var, c2w, c2b, out);
}